// round 1
// baseline (speedup 1.0000x reference)
#include <cuda_runtime.h>

#define NB   4
#define NT   4096
#define DIN  64
#define DM   256
#define BT   (NB*NT)
#define CHUNK 128
#define NCH  (NT/CHUNK)   // 32

// -------- scratch (device globals; no allocation allowed) --------
__device__ float g_h[BT*DM];            // elu(x W^T + b), 16 MB
__device__ float g_Send[NB*NCH*DM];
__device__ float g_Zend[NB*NCH];
__device__ float g_A[NB*NCH];
__device__ float g_cS[NB*NCH*DM];
__device__ float g_cZ[NB*NCH];

// -------- GEMM: h = elu(x[BT,64] @ W[256,64]^T + b) --------
// block tile 128 rows x 128 cols, 256 threads, 8x8 micro-tile
// smem row stride 68 floats (272B, 16B aligned, 17 quads; 17 % 8 == 1 -> low conflicts)
#define SMS 68
#define GSMEM (2*128*SMS*4)

__global__ __launch_bounds__(256, 1)
void gemm_elu_kernel(const float* __restrict__ x, const float* __restrict__ W,
                     const float* __restrict__ bias)
{
    extern __shared__ float sm[];
    float* xs = sm;              // [128][68]
    float* ws = sm + 128*SMS;    // [128][68]

    const int t    = threadIdx.x;
    const int row0 = blockIdx.x * 128;
    const int c0b  = blockIdx.y * 128;

    // load x tile and W tile (each 128 rows x 64 floats) via float4
    #pragma unroll
    for (int li = 0; li < 8; li++) {
        int idx = t + 256*li;          // 0..2047
        int r = idx >> 4;              // row 0..127
        int q = idx & 15;              // float4 index 0..15
        *(float4*)&xs[r*SMS + 4*q] = *(const float4*)&x[(size_t)(row0 + r)*DIN + 4*q];
        *(float4*)&ws[r*SMS + 4*q] = *(const float4*)&W[(size_t)(c0b + r)*DIN + 4*q];
    }
    __syncthreads();

    const int rg = t >> 4;   // 0..15  (rows rg + 16*i)
    const int cg = t & 15;   // 0..15  (cols cg + 16*j)

    float acc[8][8];
    #pragma unroll
    for (int i = 0; i < 8; i++)
        #pragma unroll
        for (int j = 0; j < 8; j++) acc[i][j] = 0.0f;

    #pragma unroll
    for (int k4 = 0; k4 < 16; k4++) {
        float4 xv[8];
        #pragma unroll
        for (int i = 0; i < 8; i++)
            xv[i] = *(const float4*)&xs[(rg + 16*i)*SMS + 4*k4];
        #pragma unroll
        for (int j = 0; j < 8; j++) {
            float4 wv = *(const float4*)&ws[(cg + 16*j)*SMS + 4*k4];
            #pragma unroll
            for (int i = 0; i < 8; i++) {
                acc[i][j] = fmaf(xv[i].x, wv.x, acc[i][j]);
                acc[i][j] = fmaf(xv[i].y, wv.y, acc[i][j]);
                acc[i][j] = fmaf(xv[i].z, wv.z, acc[i][j]);
                acc[i][j] = fmaf(xv[i].w, wv.w, acc[i][j]);
            }
        }
    }

    // epilogue: + bias, elu, store
    #pragma unroll
    for (int j = 0; j < 8; j++) {
        int c = c0b + cg + 16*j;
        float bj = bias[c];
        #pragma unroll
        for (int i = 0; i < 8; i++) {
            int r = row0 + rg + 16*i;
            float v = acc[i][j] + bj;
            v = (v > 0.0f) ? v : expm1f(v);
            g_h[(size_t)r*DM + c] = v;
        }
    }
}

// -------- scan phase 1: per-chunk local scan + chunk summaries --------
__global__ __launch_bounds__(256, 8)
void scan_local_kernel(const float* __restrict__ tau, const float* __restrict__ lamb)
{
    const int bc = blockIdx.x;
    const int b  = bc >> 5;        // / NCH
    const int k  = bc & (NCH-1);
    const int i0 = k * CHUNK;
    const int m  = threadIdx.x;    // 0..255

    __shared__ float ds[CHUNK];
    float lam = fmaxf(lamb[0], 0.0f);
    if (m < CHUNK)
        ds[m] = __expf(-lam * tau[b*NT + i0 + m]);
    __syncthreads();

    const float* hp = g_h + ((size_t)(b*NT + i0))*DM + m;
    float S = 0.0f, Z = 0.0f, A = 1.0f;
    #pragma unroll 8
    for (int i = 0; i < CHUNK; i++) {
        float d = ds[i];
        S = fmaf(S, d, hp[(size_t)i*DM]);
        Z = fmaf(Z, d, 1.0f);
        A *= d;
    }
    g_Send[(size_t)(b*NCH + k)*DM + m] = S;
    if (m == 0) { g_Zend[b*NCH + k] = Z; g_A[b*NCH + k] = A; }
}

// -------- scan phase 2: cross-chunk carry (tiny) --------
__global__ __launch_bounds__(256, 8)
void scan_carry_kernel()
{
    const int b = blockIdx.x;
    const int m = threadIdx.x;
    float cS = 0.0f, cZ = 0.0f;
    #pragma unroll
    for (int k = 0; k < NCH; k++) {
        g_cS[(size_t)(b*NCH + k)*DM + m] = cS;
        if (m == 0) g_cZ[b*NCH + k] = cZ;
        float A = g_A[b*NCH + k];
        cS = fmaf(cS, A, g_Send[(size_t)(b*NCH + k)*DM + m]);
        cZ = fmaf(cZ, A, g_Zend[b*NCH + k]);
    }
}

// -------- scan phase 3: finalize with carried state, write out --------
__global__ __launch_bounds__(256, 8)
void scan_final_kernel(const float* __restrict__ tau, const float* __restrict__ lamb,
                       float* __restrict__ out)
{
    const int bc = blockIdx.x;
    const int b  = bc >> 5;
    const int k  = bc & (NCH-1);
    const int i0 = k * CHUNK;
    const int m  = threadIdx.x;

    __shared__ float ds[CHUNK];
    float lam = fmaxf(lamb[0], 0.0f);
    if (m < CHUNK)
        ds[m] = __expf(-lam * tau[b*NT + i0 + m]);
    __syncthreads();

    float S = g_cS[(size_t)(b*NCH + k)*DM + m];
    float Z = g_cZ[b*NCH + k];

    const float* hp = g_h + ((size_t)(b*NT + i0))*DM + m;
    float* op = out + ((size_t)(b*NT + i0))*DM + m;
    #pragma unroll 8
    for (int i = 0; i < CHUNK; i++) {
        float d = ds[i];
        S = fmaf(S, d, hp[(size_t)i*DM]);
        Z = fmaf(Z, d, 1.0f);
        op[(size_t)i*DM] = __fdividef(S, Z);
    }
}

// -------- launch --------
extern "C" void kernel_launch(void* const* d_in, const int* in_sizes, int n_in,
                              void* d_out, int out_size)
{
    const float* x    = (const float*)d_in[0];
    const float* tau  = (const float*)d_in[1];
    const float* W    = (const float*)d_in[2];
    const float* bias = (const float*)d_in[3];
    const float* lamb = (const float*)d_in[4];
    // beta (d_in[5]) is a per-row constant shift inside softmax -> cancels exactly
    float* out = (float*)d_out;

    cudaFuncSetAttribute(gemm_elu_kernel,
                         cudaFuncAttributeMaxDynamicSharedMemorySize, GSMEM);

    gemm_elu_kernel<<<dim3(BT/128, DM/128), 256, GSMEM>>>(x, W, bias);
    scan_local_kernel<<<NB*NCH, 256>>>(tau, lamb);
    scan_carry_kernel<<<NB, 256>>>();
    scan_final_kernel<<<NB*NCH, 256>>>(tau, lamb, out);
}

// round 2
// speedup vs baseline: 1.2619x; 1.2619x over previous
#include <cuda_runtime.h>

#define NB   4
#define NT   4096
#define DIN  64
#define DM   256
#define BT   (NB*NT)
#define CHUNK 32
#define NCH  (NT/CHUNK)   // 128

// -------- scratch (device globals; no allocation allowed) --------
__device__ float g_h[BT*DM];            // elu(x W^T + b), 16 MB (L2-resident)
__device__ float g_Send[NB*NCH*DM];     // 512 KB
__device__ float g_Zend[NB*NCH];
__device__ float g_A[NB*NCH];
__device__ float g_cS[NB*NCH*DM];       // 512 KB
__device__ float g_cZ[NB*NCH];

// -------- GEMM: h = elu(x[BT,64] @ W[256,64]^T + b) --------
#define SMS 68
#define GSMEM (2*128*SMS*4)

__global__ __launch_bounds__(256, 1)
void gemm_elu_kernel(const float* __restrict__ x, const float* __restrict__ W,
                     const float* __restrict__ bias)
{
    extern __shared__ float sm[];
    float* xs = sm;              // [128][68]
    float* ws = sm + 128*SMS;    // [128][68]

    const int t    = threadIdx.x;
    const int row0 = blockIdx.x * 128;
    const int c0b  = blockIdx.y * 128;

    #pragma unroll
    for (int li = 0; li < 8; li++) {
        int idx = t + 256*li;
        int r = idx >> 4;
        int q = idx & 15;
        *(float4*)&xs[r*SMS + 4*q] = *(const float4*)&x[(size_t)(row0 + r)*DIN + 4*q];
        *(float4*)&ws[r*SMS + 4*q] = *(const float4*)&W[(size_t)(c0b + r)*DIN + 4*q];
    }
    __syncthreads();

    const int rg = t >> 4;
    const int cg = t & 15;

    float acc[8][8];
    #pragma unroll
    for (int i = 0; i < 8; i++)
        #pragma unroll
        for (int j = 0; j < 8; j++) acc[i][j] = 0.0f;

    #pragma unroll
    for (int k4 = 0; k4 < 16; k4++) {
        float4 xv[8];
        #pragma unroll
        for (int i = 0; i < 8; i++)
            xv[i] = *(const float4*)&xs[(rg + 16*i)*SMS + 4*k4];
        #pragma unroll
        for (int j = 0; j < 8; j++) {
            float4 wv = *(const float4*)&ws[(cg + 16*j)*SMS + 4*k4];
            #pragma unroll
            for (int i = 0; i < 8; i++) {
                acc[i][j] = fmaf(xv[i].x, wv.x, acc[i][j]);
                acc[i][j] = fmaf(xv[i].y, wv.y, acc[i][j]);
                acc[i][j] = fmaf(xv[i].z, wv.z, acc[i][j]);
                acc[i][j] = fmaf(xv[i].w, wv.w, acc[i][j]);
            }
        }
    }

    #pragma unroll
    for (int j = 0; j < 8; j++) {
        int c = c0b + cg + 16*j;
        float bj = bias[c];
        #pragma unroll
        for (int i = 0; i < 8; i++) {
            int r = row0 + rg + 16*i;
            float v = acc[i][j] + bj;
            v = (v > 0.0f) ? v : expm1f(v);
            g_h[(size_t)r*DM + c] = v;
        }
    }
}

// -------- scan phase 1: per-chunk local scan + chunk summaries --------
// grid = NB*NCH = 512, block = 256 (one thread per model column)
__global__ __launch_bounds__(256, 4)
void scan_local_kernel(const float* __restrict__ tau, const float* __restrict__ lamb)
{
    const int bc = blockIdx.x;
    const int b  = bc >> 7;          // / NCH
    const int k  = bc & (NCH-1);
    const int i0 = k * CHUNK;
    const int m  = threadIdx.x;

    __shared__ float ds[CHUNK];
    float lam = fmaxf(lamb[0], 0.0f);
    if (m < CHUNK)
        ds[m] = __expf(-lam * tau[b*NT + i0 + m]);

    // batch ALL chunk loads before the dependent chain -> MLP = 32
    const float* hp = g_h + ((size_t)(b*NT + i0))*DM + m;
    float hbuf[CHUNK];
    #pragma unroll
    for (int i = 0; i < CHUNK; i++) hbuf[i] = __ldg(&hp[(size_t)i*DM]);

    __syncthreads();

    float S = 0.0f, Z = 0.0f, A = 1.0f;
    #pragma unroll
    for (int i = 0; i < CHUNK; i++) {
        float d = ds[i];
        S = fmaf(S, d, hbuf[i]);
        Z = fmaf(Z, d, 1.0f);
        A *= d;
    }
    g_Send[(size_t)(b*NCH + k)*DM + m] = S;
    if (m == 0) { g_Zend[b*NCH + k] = Z; g_A[b*NCH + k] = A; }
}

// -------- scan phase 2: cross-chunk carry --------
// grid = NB, block = 256; serial over NCH=128 chunks, loads prefetched by unroll
__global__ __launch_bounds__(256, 4)
void scan_carry_kernel()
{
    const int b = blockIdx.x;
    const int m = threadIdx.x;
    float cS = 0.0f, cZ = 0.0f;
    #pragma unroll 4
    for (int k = 0; k < NCH; k++) {
        float A  = g_A[b*NCH + k];
        float Se = g_Send[(size_t)(b*NCH + k)*DM + m];
        float Ze = g_Zend[b*NCH + k];
        g_cS[(size_t)(b*NCH + k)*DM + m] = cS;
        if (m == 0) g_cZ[b*NCH + k] = cZ;
        cS = fmaf(cS, A, Se);
        cZ = fmaf(cZ, A, Ze);
    }
}

// -------- scan phase 3: finalize with carried state, write out --------
__global__ __launch_bounds__(256, 4)
void scan_final_kernel(const float* __restrict__ tau, const float* __restrict__ lamb,
                       float* __restrict__ out)
{
    const int bc = blockIdx.x;
    const int b  = bc >> 7;
    const int k  = bc & (NCH-1);
    const int i0 = k * CHUNK;
    const int m  = threadIdx.x;

    __shared__ float ds[CHUNK];
    float lam = fmaxf(lamb[0], 0.0f);
    if (m < CHUNK)
        ds[m] = __expf(-lam * tau[b*NT + i0 + m]);

    const float* hp = g_h + ((size_t)(b*NT + i0))*DM + m;
    float hbuf[CHUNK];
    #pragma unroll
    for (int i = 0; i < CHUNK; i++) hbuf[i] = __ldg(&hp[(size_t)i*DM]);

    __syncthreads();

    float S = g_cS[(size_t)(b*NCH + k)*DM + m];
    float Z = g_cZ[b*NCH + k];

    float* op = out + ((size_t)(b*NT + i0))*DM + m;
    #pragma unroll
    for (int i = 0; i < CHUNK; i++) {
        float d = ds[i];
        S = fmaf(S, d, hbuf[i]);
        Z = fmaf(Z, d, 1.0f);
        op[(size_t)i*DM] = __fdividef(S, Z);
    }
}

// -------- launch --------
extern "C" void kernel_launch(void* const* d_in, const int* in_sizes, int n_in,
                              void* d_out, int out_size)
{
    const float* x    = (const float*)d_in[0];
    const float* tau  = (const float*)d_in[1];
    const float* W    = (const float*)d_in[2];
    const float* bias = (const float*)d_in[3];
    const float* lamb = (const float*)d_in[4];
    // beta (d_in[5]) cancels in softmax (constant per row)
    float* out = (float*)d_out;

    cudaFuncSetAttribute(gemm_elu_kernel,
                         cudaFuncAttributeMaxDynamicSharedMemorySize, GSMEM);

    gemm_elu_kernel<<<dim3(BT/128, DM/128), 256, GSMEM>>>(x, W, bias);
    scan_local_kernel<<<NB*NCH, 256>>>(tau, lamb);
    scan_carry_kernel<<<NB, 256>>>();
    scan_final_kernel<<<NB*NCH, 256>>>(tau, lamb, out);
}

// round 3
// speedup vs baseline: 1.4961x; 1.1856x over previous
#include <cuda_runtime.h>

#define NB   4
#define NT   4096
#define DIN  64
#define DM   256
#define BT   (NB*NT)
#define CHUNK 32
#define NCH  (NT/CHUNK)   // 128

typedef unsigned long long ull;

// -------- scratch (device globals; no allocation allowed) --------
__device__ float g_h[BT*DM];            // elu(x W^T + b), 16 MB (L2-resident)
__device__ float g_Send[NB*NCH*DM];
__device__ float g_Zend[NB*NCH];
__device__ float g_A[NB*NCH];
__device__ float g_cS[NB*NCH*DM];
__device__ float g_cZ[NB*NCH];

// packed fp32x2 FMA (Blackwell; ptxas won't emit from C++)
static __device__ __forceinline__ void ffma2(ull &acc, ull a, ull b) {
    asm("fma.rn.f32x2 %0, %1, %2, %0;" : "+l"(acc) : "l"(a), "l"(b));
}

// -------- GEMM: h = elu(x[BT,64] @ W[256,64]^T + b) --------
// tile 128 rows x 128 cols, 512 threads, 8x4 micro-tile, K packed in f32x2
#define XSS 68           // xs stride (floats)
#define WSS 66           // ws stride (floats): (66*lane)%32 = 2*lane -> phase-conflict-free LDS.64
#define GSMEM ((128*XSS + 128*WSS)*4)

__global__ __launch_bounds__(512, 1)
void gemm_elu_kernel(const float* __restrict__ x, const float* __restrict__ W,
                     const float* __restrict__ bias)
{
    extern __shared__ float sm[];
    float* xs = sm;               // [128][XSS]  rows x k
    float* ws = sm + 128*XSS;     // [128][WSS]  cols x k

    const int t    = threadIdx.x;
    const int row0 = blockIdx.x * 128;
    const int c0b  = blockIdx.y * 128;

    // fill x tile (float4) and w tile (two float2 writes to keep 8B alignment)
    #pragma unroll
    for (int li = 0; li < 4; li++) {
        int idx = t + 512*li;          // 0..2047
        int r = idx >> 4;
        int q = idx & 15;
        *(float4*)&xs[r*XSS + 4*q] = *(const float4*)&x[(size_t)(row0 + r)*DIN + 4*q];
        float4 wv = *(const float4*)&W[(size_t)(c0b + r)*DIN + 4*q];
        *(float2*)&ws[r*WSS + 4*q]     = make_float2(wv.x, wv.y);
        *(float2*)&ws[r*WSS + 4*q + 2] = make_float2(wv.z, wv.w);
    }
    __syncthreads();

    const int r0 = t >> 5;   // 0..15 : rows r0 + 16*i
    const int c0 = t & 31;   // 0..31 : cols c0 + 32*j

    const ull* xsu = (const ull*)xs;   // stride 34 ull per row
    const ull* wsu = (const ull*)ws;   // stride 33 ull per col

    ull acc2[8][4];
    #pragma unroll
    for (int i = 0; i < 8; i++)
        #pragma unroll
        for (int j = 0; j < 4; j++) acc2[i][j] = 0ULL;

    #pragma unroll
    for (int k4 = 0; k4 < 16; k4++) {      // 4 k's = 2 f32x2 pairs per step
        const int k2 = 2*k4;
        ull wv[4][2];
        #pragma unroll
        for (int j = 0; j < 4; j++) {
            const ull* wp = &wsu[(size_t)(c0 + 32*j)*(WSS/2) + k2];
            wv[j][0] = wp[0];
            wv[j][1] = wp[1];
        }
        #pragma unroll
        for (int i = 0; i < 8; i++) {
            const ull* xp = &xsu[(size_t)(r0 + 16*i)*(XSS/2) + k2];
            ull xa = xp[0];
            ull xb = xp[1];
            #pragma unroll
            for (int j = 0; j < 4; j++) {
                ffma2(acc2[i][j], xa, wv[j][0]);
                ffma2(acc2[i][j], xb, wv[j][1]);
            }
        }
    }

    // epilogue: reduce pair, + bias, elu, store
    #pragma unroll
    for (int j = 0; j < 4; j++) {
        int c = c0b + c0 + 32*j;
        float bj = bias[c];
        #pragma unroll
        for (int i = 0; i < 8; i++) {
            int r = row0 + r0 + 16*i;
            ull a = acc2[i][j];
            float v = __uint_as_float((unsigned)a) + __uint_as_float((unsigned)(a >> 32)) + bj;
            v = (v > 0.0f) ? v : (__expf(v) - 1.0f);
            g_h[(size_t)r*DM + c] = v;
        }
    }
}

// -------- scan phase 1: per-chunk local scan + chunk summaries --------
__global__ __launch_bounds__(256, 4)
void scan_local_kernel(const float* __restrict__ tau, const float* __restrict__ lamb)
{
    const int bc = blockIdx.x;
    const int b  = bc >> 7;
    const int k  = bc & (NCH-1);
    const int i0 = k * CHUNK;
    const int m  = threadIdx.x;

    __shared__ float ds[CHUNK];
    float lam = fmaxf(lamb[0], 0.0f);
    if (m < CHUNK)
        ds[m] = __expf(-lam * tau[b*NT + i0 + m]);

    const float* hp = g_h + ((size_t)(b*NT + i0))*DM + m;
    float hbuf[CHUNK];
    #pragma unroll
    for (int i = 0; i < CHUNK; i++) hbuf[i] = __ldg(&hp[(size_t)i*DM]);

    __syncthreads();

    float S = 0.0f, Z = 0.0f, A = 1.0f;
    #pragma unroll
    for (int i = 0; i < CHUNK; i++) {
        float d = ds[i];
        S = fmaf(S, d, hbuf[i]);
        Z = fmaf(Z, d, 1.0f);
        A *= d;
    }
    g_Send[(size_t)(b*NCH + k)*DM + m] = S;
    if (m == 0) { g_Zend[b*NCH + k] = Z; g_A[b*NCH + k] = A; }
}

// -------- scan phase 2: cross-chunk carry --------
__global__ __launch_bounds__(256, 4)
void scan_carry_kernel()
{
    const int b = blockIdx.x;
    const int m = threadIdx.x;
    float cS = 0.0f, cZ = 0.0f;
    #pragma unroll 16
    for (int k = 0; k < NCH; k++) {
        float A  = g_A[b*NCH + k];
        float Se = g_Send[(size_t)(b*NCH + k)*DM + m];
        float Ze = g_Zend[b*NCH + k];
        g_cS[(size_t)(b*NCH + k)*DM + m] = cS;
        if (m == 0) g_cZ[b*NCH + k] = cZ;
        cS = fmaf(cS, A, Se);
        cZ = fmaf(cZ, A, Ze);
    }
}

// -------- scan phase 3: finalize with carried state, write out --------
__global__ __launch_bounds__(256, 4)
void scan_final_kernel(const float* __restrict__ tau, const float* __restrict__ lamb,
                       float* __restrict__ out)
{
    const int bc = blockIdx.x;
    const int b  = bc >> 7;
    const int k  = bc & (NCH-1);
    const int i0 = k * CHUNK;
    const int m  = threadIdx.x;

    __shared__ float ds[CHUNK];
    float lam = fmaxf(lamb[0], 0.0f);
    if (m < CHUNK)
        ds[m] = __expf(-lam * tau[b*NT + i0 + m]);

    const float* hp = g_h + ((size_t)(b*NT + i0))*DM + m;
    float hbuf[CHUNK];
    #pragma unroll
    for (int i = 0; i < CHUNK; i++) hbuf[i] = __ldg(&hp[(size_t)i*DM]);

    __syncthreads();

    float S = g_cS[(size_t)(b*NCH + k)*DM + m];
    float Z = g_cZ[b*NCH + k];

    float* op = out + ((size_t)(b*NT + i0))*DM + m;
    #pragma unroll
    for (int i = 0; i < CHUNK; i++) {
        float d = ds[i];
        S = fmaf(S, d, hbuf[i]);
        Z = fmaf(Z, d, 1.0f);
        op[(size_t)i*DM] = __fdividef(S, Z);
    }
}

// -------- launch --------
extern "C" void kernel_launch(void* const* d_in, const int* in_sizes, int n_in,
                              void* d_out, int out_size)
{
    const float* x    = (const float*)d_in[0];
    const float* tau  = (const float*)d_in[1];
    const float* W    = (const float*)d_in[2];
    const float* bias = (const float*)d_in[3];
    const float* lamb = (const float*)d_in[4];
    // beta (d_in[5]) cancels in softmax (constant per row)
    float* out = (float*)d_out;

    cudaFuncSetAttribute(gemm_elu_kernel,
                         cudaFuncAttributeMaxDynamicSharedMemorySize, GSMEM);

    gemm_elu_kernel<<<dim3(BT/128, DM/128), 512, GSMEM>>>(x, W, bias);
    scan_local_kernel<<<NB*NCH, 256>>>(tau, lamb);
    scan_carry_kernel<<<NB, 256>>>();
    scan_final_kernel<<<NB*NCH, 256>>>(tau, lamb, out);
}

// round 4
// speedup vs baseline: 1.5611x; 1.0434x over previous
#include <cuda_runtime.h>

#define NB   4
#define NT   4096
#define DIN  64
#define DM   256
#define BT   (NB*NT)
#define CHUNK 32
#define NCH  (NT/CHUNK)   // 128

typedef unsigned long long ull;

// -------- scratch (device globals; no allocation allowed) --------
__device__ float g_h[BT*DM];            // elu(x W^T + b), 16 MB
__device__ float g_Send[NB*NCH*DM];
__device__ float g_Zend[NB*NCH];
__device__ float g_A[NB*NCH];
__device__ float g_cS[NB*NCH*DM];
__device__ float g_cZ[NB*NCH];

// packed fp32x2 FMA (Blackwell; ptxas won't emit from C++)
static __device__ __forceinline__ void ffma2(ull &acc, ull a, ull b) {
    asm("fma.rn.f32x2 %0, %1, %2, %0;" : "+l"(acc) : "l"(a), "l"(b));
}
static __device__ __forceinline__ ull pack2(float lo, float hi) {
    ull r;
    asm("mov.b64 %0, {%1, %2};" : "=l"(r) : "f"(lo), "f"(hi));
    return r;
}

// -------- GEMM: h = elu(x[BT,64] @ W[256,64]^T + b) --------
// tile 128 rows x 256 cols (ALL of DM), 512 threads, grid = 128 blocks (1 wave)
// micro-tile: 8 rows x 4 column-PAIRS per thread, f32x2 packed along columns.
// x reads are warp-uniform broadcasts; W reads conflict-free LDS.64.
#define XSS 68                         // xs row stride (floats)
#define WP  129                        // ws2 row stride (ull), 64 rows
#define GSMEM (128*XSS*4 + 64*WP*8)    // ~99.3 KB

__global__ __launch_bounds__(512, 1)
void gemm_elu_kernel(const float* __restrict__ x, const float* __restrict__ W,
                     const float* __restrict__ bias)
{
    extern __shared__ float sm[];
    float* xs  = sm;                          // [128][XSS] rows x k
    ull*   ws2 = (ull*)(sm + 128*XSS);        // [64][WP]  k x col-pairs
    float* wsf = (float*)ws2;

    const int t    = threadIdx.x;
    const int row0 = blockIdx.x * 128;

    // fill x tile: 128 rows x 64 floats via float4 (2048 float4 / 512 thr = 4 each)
    #pragma unroll
    for (int li = 0; li < 4; li++) {
        int idx = t + 512*li;
        int r = idx >> 4;
        int q = idx & 15;
        *(float4*)&xs[r*XSS + 4*q] = *(const float4*)&x[(size_t)(row0 + r)*DIN + 4*q];
    }
    // fill W transposed: ws2[k][p] = (W[2p][k], W[2p+1][k]); 256 rows x 16 float4 each
    #pragma unroll
    for (int li = 0; li < 8; li++) {
        int idx = t + 512*li;          // 0..4095
        int c = idx >> 4;              // 0..255
        int q = idx & 15;
        float4 wv = *(const float4*)&W[(size_t)c*DIN + 4*q];
        int p = c >> 1, wd = c & 1;
        wsf[((4*q+0)*WP + p)*2 + wd] = wv.x;
        wsf[((4*q+1)*WP + p)*2 + wd] = wv.y;
        wsf[((4*q+2)*WP + p)*2 + wd] = wv.z;
        wsf[((4*q+3)*WP + p)*2 + wd] = wv.w;
    }
    __syncthreads();

    const int r0 = t >> 5;   // 0..15 (warp-uniform) : rows r0 + 16*i
    const int c0 = t & 31;   // 0..31 : col-pairs c0 + 32*j

    ull acc2[8][4];
    #pragma unroll
    for (int i = 0; i < 8; i++)
        #pragma unroll
        for (int j = 0; j < 4; j++) acc2[i][j] = 0ULL;

    #pragma unroll 4
    for (int k = 0; k < DIN; k++) {
        ull wv[4];
        #pragma unroll
        for (int j = 0; j < 4; j++)
            wv[j] = ws2[(size_t)k*WP + c0 + 32*j];
        #pragma unroll
        for (int i = 0; i < 8; i++) {
            float xv = xs[(r0 + 16*i)*XSS + k];   // warp-broadcast
            ull xx = pack2(xv, xv);
            #pragma unroll
            for (int j = 0; j < 4; j++)
                ffma2(acc2[i][j], xx, wv[j]);
        }
    }

    // epilogue: + bias, elu, float2 store (adjacent cols -> coalesced)
    #pragma unroll
    for (int j = 0; j < 4; j++) {
        int p = c0 + 32*j;               // pair -> cols 2p, 2p+1
        float2 bj = *(const float2*)&bias[2*p];
        #pragma unroll
        for (int i = 0; i < 8; i++) {
            int r = row0 + r0 + 16*i;
            ull a = acc2[i][j];
            float v0 = __uint_as_float((unsigned)a)        + bj.x;
            float v1 = __uint_as_float((unsigned)(a >> 32)) + bj.y;
            v0 = (v0 > 0.0f) ? v0 : (__expf(v0) - 1.0f);
            v1 = (v1 > 0.0f) ? v1 : (__expf(v1) - 1.0f);
            *(float2*)&g_h[(size_t)r*DM + 2*p] = make_float2(v0, v1);
        }
    }
}

// -------- scan phase 1: per-chunk local scan + chunk summaries --------
__global__ __launch_bounds__(256, 4)
void scan_local_kernel(const float* __restrict__ tau, const float* __restrict__ lamb)
{
    const int bc = blockIdx.x;
    const int b  = bc >> 7;
    const int k  = bc & (NCH-1);
    const int i0 = k * CHUNK;
    const int m  = threadIdx.x;

    __shared__ float ds[CHUNK];
    float lam = fmaxf(lamb[0], 0.0f);
    if (m < CHUNK)
        ds[m] = __expf(-lam * tau[b*NT + i0 + m]);

    const float* hp = g_h + ((size_t)(b*NT + i0))*DM + m;
    float hbuf[CHUNK];
    #pragma unroll
    for (int i = 0; i < CHUNK; i++) hbuf[i] = __ldg(&hp[(size_t)i*DM]);

    __syncthreads();

    float S = 0.0f, Z = 0.0f, A = 1.0f;
    #pragma unroll
    for (int i = 0; i < CHUNK; i++) {
        float d = ds[i];
        S = fmaf(S, d, hbuf[i]);
        Z = fmaf(Z, d, 1.0f);
        A *= d;
    }
    g_Send[(size_t)(b*NCH + k)*DM + m] = S;
    if (m == 0) { g_Zend[b*NCH + k] = Z; g_A[b*NCH + k] = A; }
}

// -------- scan phase 2: cross-chunk carry --------
__global__ __launch_bounds__(256, 4)
void scan_carry_kernel()
{
    const int b = blockIdx.x;
    const int m = threadIdx.x;
    float cS = 0.0f, cZ = 0.0f;
    #pragma unroll 16
    for (int k = 0; k < NCH; k++) {
        float A  = g_A[b*NCH + k];
        float Se = g_Send[(size_t)(b*NCH + k)*DM + m];
        float Ze = g_Zend[b*NCH + k];
        g_cS[(size_t)(b*NCH + k)*DM + m] = cS;
        if (m == 0) g_cZ[b*NCH + k] = cZ;
        cS = fmaf(cS, A, Se);
        cZ = fmaf(cZ, A, Ze);
    }
}

// -------- scan phase 3: finalize with carried state, write out --------
__global__ __launch_bounds__(256, 4)
void scan_final_kernel(const float* __restrict__ tau, const float* __restrict__ lamb,
                       float* __restrict__ out)
{
    const int bc = blockIdx.x;
    const int b  = bc >> 7;
    const int k  = bc & (NCH-1);
    const int i0 = k * CHUNK;
    const int m  = threadIdx.x;

    __shared__ float ds[CHUNK];
    float lam = fmaxf(lamb[0], 0.0f);
    if (m < CHUNK)
        ds[m] = __expf(-lam * tau[b*NT + i0 + m]);

    const float* hp = g_h + ((size_t)(b*NT + i0))*DM + m;
    float hbuf[CHUNK];
    #pragma unroll
    for (int i = 0; i < CHUNK; i++) hbuf[i] = __ldg(&hp[(size_t)i*DM]);

    __syncthreads();

    float S = g_cS[(size_t)(b*NCH + k)*DM + m];
    float Z = g_cZ[b*NCH + k];

    float* op = out + ((size_t)(b*NT + i0))*DM + m;
    #pragma unroll
    for (int i = 0; i < CHUNK; i++) {
        float d = ds[i];
        S = fmaf(S, d, hbuf[i]);
        Z = fmaf(Z, d, 1.0f);
        op[(size_t)i*DM] = __fdividef(S, Z);
    }
}

// -------- launch --------
extern "C" void kernel_launch(void* const* d_in, const int* in_sizes, int n_in,
                              void* d_out, int out_size)
{
    const float* x    = (const float*)d_in[0];
    const float* tau  = (const float*)d_in[1];
    const float* W    = (const float*)d_in[2];
    const float* bias = (const float*)d_in[3];
    const float* lamb = (const float*)d_in[4];
    // beta (d_in[5]) cancels in softmax (constant per row)
    float* out = (float*)d_out;

    cudaFuncSetAttribute(gemm_elu_kernel,
                         cudaFuncAttributeMaxDynamicSharedMemorySize, GSMEM);

    gemm_elu_kernel<<<BT/128, 512, GSMEM>>>(x, W, bias);
    scan_local_kernel<<<NB*NCH, 256>>>(tau, lamb);
    scan_carry_kernel<<<NB, 256>>>();
    scan_final_kernel<<<NB*NCH, 256>>>(tau, lamb, out);
}

// round 5
// speedup vs baseline: 2.1095x; 1.3512x over previous
#include <cuda_runtime.h>

#define NB   4
#define NT   4096
#define DIN  64
#define DM   256
#define BT   (NB*NT)
#define BLK  128                 // rows per block = chunk length
#define NCHB (NT/BLK)            // 32 chunks per batch
#define NBLK (BT/BLK)            // 128 blocks total

typedef unsigned long long ull;

// -------- globals (zero-init; no allocation allowed) --------
__device__ float g_S[NBLK*DM];   // per-chunk aggregate S_end
__device__ float g_Zc[NBLK];     // per-chunk aggregate Z_end
__device__ float g_Ac[NBLK];     // per-chunk decay product
__device__ int   g_flag[NBLK];   // epoch-stamped ready flags
__device__ int   g_epoch;

__global__ void bump_epoch_kernel() { g_epoch = g_epoch + 1; }

// packed fp32x2 FMA (Blackwell; ptxas won't emit from C++)
static __device__ __forceinline__ void ffma2(ull &acc, ull a, ull b) {
    asm("fma.rn.f32x2 %0, %1, %2, %0;" : "+l"(acc) : "l"(a), "l"(b));
}
static __device__ __forceinline__ ull pack2(float lo, float hi) {
    ull r;
    asm("mov.b64 %0, {%1, %2};" : "=l"(r) : "f"(lo), "f"(hi));
    return r;
}

// -------- smem layout (union of GEMM and SCAN phases) --------
#define XSS 68                        // x tile row stride (floats)
#define WP  129                       // W-pair tile row stride (ull)
#define GEMM_BYTES (128*XSS*4 + 64*WP*8)   // 100864
#define HSS 264                       // h tile row stride (floats)
#define SCAN_BYTES (128*HSS*4 + 128*4)     // 135680
#define GSMEM SCAN_BYTES

// ==================================================================
// Fused: GEMM(+bias,+elu) -> smem h -> local scan -> decoupled
// lookback over same-batch predecessors -> finalize -> out.
// grid = 128 (one wave, co-resident), block = 512.
// ==================================================================
__global__ __launch_bounds__(512, 1)
void fused_kernel(const float* __restrict__ x, const float* __restrict__ tau,
                  const float* __restrict__ W, const float* __restrict__ bias,
                  const float* __restrict__ lamb, float* __restrict__ out)
{
    extern __shared__ float sm[];
    float* xs  = sm;                     // [128][XSS]
    ull*   ws2 = (ull*)(sm + 128*XSS);   // [64][WP]
    float* wsf = (float*)ws2;
    float* hs  = sm;                     // [128][HSS] (after GEMM)
    float* ds  = sm + 128*HSS;           // [128]

    __shared__ int s_epoch;

    const int t    = threadIdx.x;
    const int blk  = blockIdx.x;
    const int row0 = blk * BLK;          // global row
    const int kk   = blk & (NCHB-1);     // chunk within batch
    const int base = blk - kk;           // batch's first block id

    if (t == 0) s_epoch = g_epoch;

    // ---- load GEMM tiles ----
    #pragma unroll
    for (int li = 0; li < 4; li++) {
        int idx = t + 512*li;
        int r = idx >> 4;
        int q = idx & 15;
        *(float4*)&xs[r*XSS + 4*q] = *(const float4*)&x[(size_t)(row0 + r)*DIN + 4*q];
    }
    #pragma unroll
    for (int li = 0; li < 8; li++) {
        int idx = t + 512*li;          // 0..4095
        int c = idx >> 4;              // 0..255
        int q = idx & 15;
        float4 wv = *(const float4*)&W[(size_t)c*DIN + 4*q];
        int p = c >> 1, wd = c & 1;
        wsf[((4*q+0)*WP + p)*2 + wd] = wv.x;
        wsf[((4*q+1)*WP + p)*2 + wd] = wv.y;
        wsf[((4*q+2)*WP + p)*2 + wd] = wv.z;
        wsf[((4*q+3)*WP + p)*2 + wd] = wv.w;
    }
    __syncthreads();

    // ---- GEMM compute: 8 rows x 4 col-pairs per thread, f32x2 over col pairs ----
    const int r0 = t >> 5;   // warp-uniform row group
    const int c0 = t & 31;   // col-pair lane

    ull acc2[8][4];
    #pragma unroll
    for (int i = 0; i < 8; i++)
        #pragma unroll
        for (int j = 0; j < 4; j++) acc2[i][j] = 0ULL;

    #pragma unroll 4
    for (int k = 0; k < DIN; k++) {
        ull wv[4];
        #pragma unroll
        for (int j = 0; j < 4; j++)
            wv[j] = ws2[(size_t)k*WP + c0 + 32*j];
        #pragma unroll
        for (int i = 0; i < 8; i++) {
            float xv = xs[(r0 + 16*i)*XSS + k];   // warp-broadcast
            ull xx = pack2(xv, xv);
            #pragma unroll
            for (int j = 0; j < 4; j++)
                ffma2(acc2[i][j], xx, wv[j]);
        }
    }
    __syncthreads();   // tiles dead; smem becomes h tile

    // ---- epilogue: +bias, elu, write h into smem ----
    #pragma unroll
    for (int j = 0; j < 4; j++) {
        int p = c0 + 32*j;
        float2 bj = *(const float2*)&bias[2*p];
        #pragma unroll
        for (int i = 0; i < 8; i++) {
            int r = r0 + 16*i;
            ull a = acc2[i][j];
            float v0 = __uint_as_float((unsigned)a)         + bj.x;
            float v1 = __uint_as_float((unsigned)(a >> 32)) + bj.y;
            v0 = (v0 > 0.0f) ? v0 : (__expf(v0) - 1.0f);
            v1 = (v1 > 0.0f) ? v1 : (__expf(v1) - 1.0f);
            *(float2*)&hs[r*HSS + 2*p] = make_float2(v0, v1);
        }
    }
    // decay factors for this chunk
    if (t < BLK) {
        float lam = fmaxf(lamb[0], 0.0f);
        ds[t] = __expf(-lam * tau[row0 + t]);
    }
    __syncthreads();

    const int m = t;   // column (threads 0..255 active for scan math)
    const int e = s_epoch;

    // ---- local scan + publish aggregates ----
    float S = 0.0f, Z = 0.0f, A = 1.0f;
    if (m < DM) {
        #pragma unroll 8
        for (int i = 0; i < BLK; i++) {
            float d = ds[i];
            S = fmaf(S, d, hs[i*HSS + m]);
            Z = fmaf(Z, d, 1.0f);
            A *= d;
        }
        g_S[(size_t)blk*DM + m] = S;
        if (m == 0) { g_Zc[blk] = Z; g_Ac[blk] = A; }
        __threadfence();
    }
    __syncthreads();
    if (t == 0) *(volatile int*)&g_flag[blk] = e;   // release

    // ---- decoupled lookback over same-batch predecessors ----
    float cS = 0.0f, cZ = 0.0f;
    if (kk > 0) {
        int ok;
        do {
            ok = (t < kk) ? (*(volatile int*)&g_flag[base + t] == e) : 1;
        } while (!__syncthreads_and(ok));
        __threadfence();   // acquire: order data reads after flag observation

        if (m < DM) {
            float Ap = 1.0f;
            for (int j = kk - 1; j >= 0; j--) {
                float Sj = g_S[(size_t)(base + j)*DM + m];
                float Zj = g_Zc[base + j];
                float Aj = g_Ac[base + j];
                cS = fmaf(Ap, Sj, cS);
                cZ = fmaf(Ap, Zj, cZ);
                Ap *= Aj;
            }
        }
    }

    // ---- finalize with carry, write output ----
    if (m < DM) {
        float Sf = cS, Zf = cZ;
        float* op = out + (size_t)row0*DM + m;
        #pragma unroll 8
        for (int i = 0; i < BLK; i++) {
            float d = ds[i];
            Sf = fmaf(Sf, d, hs[i*HSS + m]);
            Zf = fmaf(Zf, d, 1.0f);
            op[(size_t)i*DM] = __fdividef(Sf, Zf);
        }
    }
}

// -------- launch --------
extern "C" void kernel_launch(void* const* d_in, const int* in_sizes, int n_in,
                              void* d_out, int out_size)
{
    const float* x    = (const float*)d_in[0];
    const float* tau  = (const float*)d_in[1];
    const float* W    = (const float*)d_in[2];
    const float* bias = (const float*)d_in[3];
    const float* lamb = (const float*)d_in[4];
    // beta (d_in[5]) cancels in softmax (constant per row)
    float* out = (float*)d_out;

    cudaFuncSetAttribute(fused_kernel,
                         cudaFuncAttributeMaxDynamicSharedMemorySize, GSMEM);

    bump_epoch_kernel<<<1, 1>>>();
    fused_kernel<<<NBLK, 512, GSMEM>>>(x, tau, W, bias, lamb, out);
}

// round 6
// speedup vs baseline: 2.3043x; 1.0924x over previous
#include <cuda_runtime.h>

#define NB   4
#define NT   4096
#define DIN  64
#define DM   256
#define BT   (NB*NT)
#define BLK  128                 // rows per block (chunk)
#define HALF 64                  // rows per half-scan
#define NCHB (NT/BLK)            // 32 chunks per batch
#define NBLK (BT/BLK)            // 128 blocks total

typedef unsigned long long ull;

// -------- globals (no allocation allowed) --------
__device__ float g_S[NBLK*DM];
__device__ float g_Zc[NBLK];
__device__ float g_Ac[NBLK];
__device__ int   g_flag[NBLK];
__device__ int   g_epoch;

__global__ void bump_epoch_kernel() { g_epoch = g_epoch + 1; }

// packed fp32x2 FMA (Blackwell; ptxas won't emit from C++)
static __device__ __forceinline__ void ffma2(ull &acc, ull a, ull b) {
    asm("fma.rn.f32x2 %0, %1, %2, %0;" : "+l"(acc) : "l"(a), "l"(b));
}
static __device__ __forceinline__ ull pack2(float lo, float hi) {
    ull r;
    asm("mov.b64 %0, {%1, %2};" : "=l"(r) : "f"(lo), "f"(hi));
    return r;
}

// -------- smem layout (GEMM tiles overlaid by h tile) --------
#define XSS 68                        // x tile row stride (floats)
#define WP  129                       // W-pair tile row stride (ull)
#define HSS 264                       // h tile row stride (floats)
// after h tile: ds[128], shS0[256], sA[32], sZ[32], sAp[32], ssc[4]
#define GSMEM (128*HSS*4 + (128 + 256 + 32 + 32 + 32 + 4)*4)

__global__ __launch_bounds__(512, 1)
void fused_kernel(const float* __restrict__ x, const float* __restrict__ tau,
                  const float* __restrict__ W, const float* __restrict__ bias,
                  const float* __restrict__ lamb, float* __restrict__ out)
{
    extern __shared__ float sm[];
    float* xs   = sm;                     // GEMM phase
    ull*   ws2  = (ull*)(sm + 128*XSS);
    float* wsf  = (float*)ws2;
    float* hs   = sm;                     // scan phase (overlays tiles)
    float* ds   = sm + 128*HSS;           // [128] decays
    float* shS0 = ds + 128;               // [256] half-0 aggregate S
    float* sA   = shS0 + 256;             // [32] predecessor A
    float* sZ   = sA + 32;                // [32] predecessor Z
    float* sAp  = sZ + 32;                // [32] suffix products
    float* ssc  = sAp + 32;               // [0]=Z0 [1]=A0 [2]=cZ

    __shared__ int s_epoch;

    const int t    = threadIdx.x;
    const int blk  = blockIdx.x;
    const int row0 = blk * BLK;
    const int kk   = blk & (NCHB-1);
    const int base = blk - kk;
    const int half = t >> 8;             // 0/1
    const int m    = t & 255;            // column

    if (t == 0) s_epoch = g_epoch;

    // ---- decays first (region disjoint from GEMM tiles; hides under tile loads)
    if (t < BLK) {
        float lam = fmaxf(__ldg(&lamb[0]), 0.0f);
        ds[t] = __expf(-lam * __ldg(&tau[row0 + t]));
    }

    // ---- GEMM tile loads ----
    #pragma unroll
    for (int li = 0; li < 4; li++) {
        int idx = t + 512*li;
        int r = idx >> 4;
        int q = idx & 15;
        *(float4*)&xs[r*XSS + 4*q] = *(const float4*)&x[(size_t)(row0 + r)*DIN + 4*q];
    }
    #pragma unroll
    for (int li = 0; li < 8; li++) {
        int idx = t + 512*li;
        int c = idx >> 4;
        int q = idx & 15;
        float4 wv = *(const float4*)&W[(size_t)c*DIN + 4*q];
        int p = c >> 1, wd = c & 1;
        wsf[((4*q+0)*WP + p)*2 + wd] = wv.x;
        wsf[((4*q+1)*WP + p)*2 + wd] = wv.y;
        wsf[((4*q+2)*WP + p)*2 + wd] = wv.z;
        wsf[((4*q+3)*WP + p)*2 + wd] = wv.w;
    }
    __syncthreads();

    // ---- GEMM: 8 rows x 4 col-pairs / thread, f32x2 over col pairs ----
    const int r0 = t >> 5;
    const int c0 = t & 31;

    ull acc2[8][4];
    #pragma unroll
    for (int i = 0; i < 8; i++)
        #pragma unroll
        for (int j = 0; j < 4; j++) acc2[i][j] = 0ULL;

    #pragma unroll 4
    for (int k = 0; k < DIN; k++) {
        ull wv[4];
        #pragma unroll
        for (int j = 0; j < 4; j++)
            wv[j] = ws2[(size_t)k*WP + c0 + 32*j];
        #pragma unroll
        for (int i = 0; i < 8; i++) {
            float xv = xs[(r0 + 16*i)*XSS + k];
            ull xx = pack2(xv, xv);
            #pragma unroll
            for (int j = 0; j < 4; j++)
                ffma2(acc2[i][j], xx, wv[j]);
        }
    }
    __syncthreads();   // tiles dead -> h tile

    // ---- epilogue: +bias, elu -> smem h ----
    #pragma unroll
    for (int j = 0; j < 4; j++) {
        int p = c0 + 32*j;
        float2 bj = *(const float2*)&bias[2*p];
        #pragma unroll
        for (int i = 0; i < 8; i++) {
            int r = r0 + 16*i;
            ull a = acc2[i][j];
            float v0 = __uint_as_float((unsigned)a)         + bj.x;
            float v1 = __uint_as_float((unsigned)(a >> 32)) + bj.y;
            v0 = (v0 > 0.0f) ? v0 : (__expf(v0) - 1.0f);
            v1 = (v1 > 0.0f) ? v1 : (__expf(v1) - 1.0f);
            *(float2*)&hs[r*HSS + 2*p] = make_float2(v0, v1);
        }
    }
    __syncthreads();

    // ---- local scan, split across halves (64 rows each, all 512 threads) ----
    const int i0 = half * HALF;
    float S = 0.0f, Z = 0.0f, A = 1.0f;
    #pragma unroll 8
    for (int i = 0; i < HALF; i++) {
        float d = ds[i0 + i];
        S = fmaf(S, d, hs[(i0 + i)*HSS + m]);
        Z = fmaf(Z, d, 1.0f);
        A *= d;
    }
    if (half == 0) {
        shS0[m] = S;
        if (m == 0) { ssc[0] = Z; ssc[1] = A; }
    }
    __syncthreads();

    // ---- half-1 publishes combined block aggregate ----
    const int e = s_epoch;
    if (half == 1) {
        g_S[(size_t)blk*DM + m] = fmaf(shS0[m], A, S);
        if (m == 0) {
            g_Zc[blk] = fmaf(ssc[0], A, Z);
            g_Ac[blk] = ssc[1] * A;
        }
        __threadfence();
    }
    __syncthreads();
    if (t == 0) *(volatile int*)&g_flag[blk] = e;   // release

    // ---- parallel lookback ----
    float cS = 0.0f, cZ = 0.0f;
    if (kk > 0) {
        int ok;
        do {
            ok = (t < kk) ? (*(volatile int*)&g_flag[base + t] == e) : 1;
        } while (!__syncthreads_and(ok));
        __threadfence();   // acquire

        if (t < kk) { sA[t] = g_Ac[base + t]; sZ[t] = g_Zc[base + t]; }
        __syncthreads();
        if (t == 0) {       // suffix products + scalar cZ (<=31 fmas)
            float Ap = 1.0f, z = 0.0f;
            for (int j = kk - 1; j >= 0; j--) {
                sAp[j] = Ap;
                z = fmaf(Ap, sZ[j], z);
                Ap *= sA[j];
            }
            ssc[2] = z;
        }
        __syncthreads();

        // independent loads across j -> fully pipelined
        const float* gsb = g_S + (size_t)base*DM + m;
        #pragma unroll 4
        for (int j = 0; j < kk; j++)
            cS = fmaf(sAp[j], __ldg(&gsb[(size_t)j*DM]), cS);
        cZ = ssc[2];
    }

    // ---- finalize per half, write out ----
    float Sf, Zf;
    if (half == 0) { Sf = cS; Zf = cZ; }
    else {
        float A0 = ssc[1];
        Sf = fmaf(cS, A0, shS0[m]);
        Zf = fmaf(cZ, A0, ssc[0]);
    }
    float* op = out + (size_t)(row0 + i0)*DM + m;
    #pragma unroll 8
    for (int i = 0; i < HALF; i++) {
        float d = ds[i0 + i];
        Sf = fmaf(Sf, d, hs[(i0 + i)*HSS + m]);
        Zf = fmaf(Zf, d, 1.0f);
        op[(size_t)i*DM] = __fdividef(Sf, Zf);
    }
}

// -------- launch --------
extern "C" void kernel_launch(void* const* d_in, const int* in_sizes, int n_in,
                              void* d_out, int out_size)
{
    const float* x    = (const float*)d_in[0];
    const float* tau  = (const float*)d_in[1];
    const float* W    = (const float*)d_in[2];
    const float* bias = (const float*)d_in[3];
    const float* lamb = (const float*)d_in[4];
    // beta (d_in[5]) cancels in softmax (constant per row)
    float* out = (float*)d_out;

    cudaFuncSetAttribute(fused_kernel,
                         cudaFuncAttributeMaxDynamicSharedMemorySize, GSMEM);

    bump_epoch_kernel<<<1, 1>>>();
    fused_kernel<<<NBLK, 512, GSMEM>>>(x, tau, W, bias, lamb, out);
}